// round 4
// baseline (speedup 1.0000x reference)
#include <cuda_runtime.h>
#include <math.h>

#define Bn 128
#define Tn 512
#define Dn 1024
#define Hn 1024
#define NBLK 128          // persistent recurrence CTAs (single wave on 148 SMs)
#define TPB  256

// ---------------- device scratch (no allocations allowed) ----------------
__device__ float g_xg[(size_t)Tn * 4 * Bn * Hn];   // [t][g][b][h]  (1 GiB)
__device__ float g_h[2][Bn * Hn];                  // ping-pong hidden state
__device__ unsigned g_bar_count;                   // grid barrier (generation-based)
__device__ unsigned g_bar_gen;

// ---------------- init: zero h0 (c lives in registers) ----------------
__global__ void init_kernel() {
    int i = blockIdx.x * blockDim.x + threadIdx.x;
    if (i < Bn * Hn) g_h[0][i] = 0.0f;
}

// ---------------- software grid barrier (atomic acquire/release) ----------------
__device__ __forceinline__ void grid_sync() {
    __threadfence();
    __syncthreads();
    if (threadIdx.x == 0) {
        unsigned gen = atomicAdd(&g_bar_gen, 0u);          // strong read
        if (atomicAdd(&g_bar_count, 1u) == NBLK - 1) {
            g_bar_count = 0;
            __threadfence();
            atomicExch(&g_bar_gen, gen + 1);               // release
        } else {
            int backoff = 32;
            while (atomicAdd(&g_bar_gen, 0u) == gen) {
                __nanosleep(backoff);
                if (backoff < 1024) backoff <<= 1;
            }
            __threadfence();                               // acquire
        }
    }
    __syncthreads();
}

// =====================================================================
// Phase 1: xg[t][g][b][h] = sum_d x[b][t][d] * Wx[g][d][h]
// grid = 65536 (t*128 + tile); tile = 32 b x 128 cols (4 gates x 32 h)
// 256 threads, 4x4 micro-tile; A-frag warp-broadcast LDS.128,
// B-frag one LDS.128; register-prefetch pipeline over K-panels of 16.
// =====================================================================
__global__ __launch_bounds__(TPB) void xg_gemm(const float* __restrict__ x,
                                               const float* __restrict__ Wx) {
    const int bid = blockIdx.x;
    const int t   = bid >> 7;
    const int r   = bid & 127;
    const int b0  = (r >> 5) * 32;
    const int h0  = (r & 31) * 32;

    __shared__ float  As[16][36];     // [k][b]; 36-stride keeps float4 rows aligned
    __shared__ float4 Bs4[16][32];    // [k][col4], col = g*32 + hh

    const int tid = threadIdx.x;
    const int tx  = tid & 31;         // col group: cols 4tx..4tx+3
    const int ty  = tid >> 5;         // row group: rows 4ty..4ty+3 (uniform per warp)
    const int g   = tx >> 3;
    const int hh0 = (tx & 7) * 4;

    const int a_b0 = tid & 31,  a_k0 = tid >> 5;
    const int b_c4a = tid & 31, b_kka = tid >> 5;
    const int b_c4b = tid & 31, b_kkb = (tid >> 5) + 8;
    const int b_ga = b_c4a >> 3, b_hha = (b_c4a & 7) * 4;
    const int b_gb = b_c4b >> 3, b_hhb = (b_c4b & 7) * 4;

    const float*  xrow = x + (size_t)t * Dn;
    const float4* wa = (const float4*)(Wx + (size_t)b_ga * Dn * Hn + h0 + b_hha);
    const float4* wb = (const float4*)(Wx + (size_t)b_gb * Dn * Hn + h0 + b_hhb);

    float acc[4][4] = {};

    float  ra0 = xrow[(size_t)(b0 + a_b0) * (Tn * Dn) + a_k0];
    float  ra1 = xrow[(size_t)(b0 + a_b0) * (Tn * Dn) + a_k0 + 8];
    float4 rb0 = wa[(size_t)b_kka * (Hn / 4)];
    float4 rb1 = wb[(size_t)b_kkb * (Hn / 4)];

    for (int k0 = 0; k0 < Dn; k0 += 16) {
        As[a_k0][a_b0]     = ra0;
        As[a_k0 + 8][a_b0] = ra1;
        Bs4[b_kka][b_c4a]  = rb0;
        Bs4[b_kkb][b_c4b]  = rb1;
        __syncthreads();

        if (k0 + 16 < Dn) {
            ra0 = xrow[(size_t)(b0 + a_b0) * (Tn * Dn) + k0 + 16 + a_k0];
            ra1 = xrow[(size_t)(b0 + a_b0) * (Tn * Dn) + k0 + 16 + a_k0 + 8];
            rb0 = wa[(size_t)(k0 + 16 + b_kka) * (Hn / 4)];
            rb1 = wb[(size_t)(k0 + 16 + b_kkb) * (Hn / 4)];
        }
#pragma unroll
        for (int k = 0; k < 16; k++) {
            float4 av = *(const float4*)&As[k][ty * 4];   // warp-broadcast
            float4 bv = Bs4[k][tx];
            float a[4] = {av.x, av.y, av.z, av.w};
            float b[4] = {bv.x, bv.y, bv.z, bv.w};
#pragma unroll
            for (int i = 0; i < 4; i++)
#pragma unroll
                for (int j = 0; j < 4; j++)
                    acc[i][j] = fmaf(a[i], b[j], acc[i][j]);
        }
        __syncthreads();
    }

    float* out = g_xg + ((size_t)t * 4 + g) * (size_t)(Bn * Hn);
#pragma unroll
    for (int i = 0; i < 4; i++) {
        float4 v = make_float4(acc[i][0], acc[i][1], acc[i][2], acc[i][3]);
        *(float4*)&out[(size_t)(b0 + 4 * ty + i) * Hn + h0 + hh0] = v;
    }
}

// =====================================================================
// Phase 2: persistent recurrence. 128 CTAs, each owns a fixed 32x32 (b,h)
// patch; c stays in registers for the whole sequence. One grid barrier/step.
// =====================================================================
__global__ __launch_bounds__(TPB) void recur_kernel(const float* __restrict__ Wh,
                                                    const float* __restrict__ bias,
                                                    float* __restrict__ out) {
    const int bid = blockIdx.x;                 // 0..127
    const int b0  = (bid >> 5) * 32;
    const int h0  = (bid & 31) * 32;

    __shared__ float  As[16][36];
    __shared__ float4 Bs4[16][32];
    __shared__ float  gsm[4][32][36];           // staged gate pre-activations

    const int tid = threadIdx.x;
    const int tx  = tid & 31;
    const int ty  = tid >> 5;
    const int g   = tx >> 3;
    const int hh0 = (tx & 7) * 4;

    const int a_b0 = tid & 31, a_k0 = tid >> 5;
    const int b_c4a = tid & 31, b_kka = tid >> 5;
    const int b_c4b = tid & 31, b_kkb = (tid >> 5) + 8;
    const int b_ga = b_c4a >> 3, b_hha = (b_c4a & 7) * 4;
    const int b_gb = b_c4b >> 3, b_hhb = (b_c4b & 7) * 4;

    const float4* wa = (const float4*)(Wh + (size_t)b_ga * Hn * Hn + h0 + b_hha);
    const float4* wb = (const float4*)(Wh + (size_t)b_gb * Hn * Hn + h0 + b_hhb);

    const float4 bi = *(const float4*)&bias[g * Hn + h0 + hh0];

    const int ub = tid >> 3;          // owned cell row
    const int uh = (tid & 7) * 4;     // owned cell cols
    float c[4] = {0.f, 0.f, 0.f, 0.f};

    for (int t = 0; t < Tn; t++) {
        const float* hprev = g_h[t & 1];
        float acc[4][4] = {};

        float  ra0 = hprev[(size_t)(b0 + a_b0) * Hn + a_k0];
        float  ra1 = hprev[(size_t)(b0 + a_b0) * Hn + a_k0 + 8];
        float4 rb0 = wa[(size_t)b_kka * (Hn / 4)];
        float4 rb1 = wb[(size_t)b_kkb * (Hn / 4)];

        for (int k0 = 0; k0 < Hn; k0 += 16) {
            As[a_k0][a_b0]     = ra0;
            As[a_k0 + 8][a_b0] = ra1;
            Bs4[b_kka][b_c4a]  = rb0;
            Bs4[b_kkb][b_c4b]  = rb1;
            __syncthreads();

            if (k0 + 16 < Hn) {
                ra0 = hprev[(size_t)(b0 + a_b0) * Hn + k0 + 16 + a_k0];
                ra1 = hprev[(size_t)(b0 + a_b0) * Hn + k0 + 16 + a_k0 + 8];
                rb0 = wa[(size_t)(k0 + 16 + b_kka) * (Hn / 4)];
                rb1 = wb[(size_t)(k0 + 16 + b_kkb) * (Hn / 4)];
            }
#pragma unroll
            for (int k = 0; k < 16; k++) {
                float4 av = *(const float4*)&As[k][ty * 4];
                float4 bv = Bs4[k][tx];
                float a[4] = {av.x, av.y, av.z, av.w};
                float b[4] = {bv.x, bv.y, bv.z, bv.w};
#pragma unroll
                for (int i = 0; i < 4; i++)
#pragma unroll
                    for (int j = 0; j < 4; j++)
                        acc[i][j] = fmaf(a[i], b[j], acc[i][j]);
            }
            __syncthreads();
        }

        // epilogue: gates = acc + xg + bias -> smem
        const float* xg = g_xg + ((size_t)t * 4 + g) * (size_t)(Bn * Hn);
#pragma unroll
        for (int i = 0; i < 4; i++) {
            float4 xv = *(const float4*)&xg[(size_t)(b0 + 4 * ty + i) * Hn + h0 + hh0];
            float* dst = &gsm[g][4 * ty + i][hh0];
            dst[0] = acc[i][0] + xv.x + bi.x;
            dst[1] = acc[i][1] + xv.y + bi.y;
            dst[2] = acc[i][2] + xv.z + bi.z;
            dst[3] = acc[i][3] + xv.w + bi.w;
        }
        __syncthreads();

        // cell update on owned elements
        float hv[4];
#pragma unroll
        for (int e = 0; e < 4; e++) {
            float gi = gsm[0][ub][uh + e];
            float gf = gsm[1][ub][uh + e];
            float go = gsm[2][ub][uh + e];
            float gu = gsm[3][ub][uh + e];
            float i_ = 1.0f / (1.0f + expf(-gi));
            float f_ = 1.0f / (1.0f + expf(-gf));
            float o_ = 1.0f / (1.0f + expf(-go));
            float u_ = tanhf(gu);
            c[e] = f_ * c[e] + i_ * u_;
            hv[e] = o_ * tanhf(c[e]);
        }
        float4 hq = make_float4(hv[0], hv[1], hv[2], hv[3]);
        if (t == Tn - 1) {
            *(float4*)&out[(size_t)(b0 + ub) * Hn + h0 + uh] = hq;
        } else {
            *(float4*)&g_h[(t + 1) & 1][(size_t)(b0 + ub) * Hn + h0 + uh] = hq;
        }

        grid_sync();   // publish h; also guards gsm reuse next step
    }
}

// ---------------- launch: 3 graph nodes total ----------------
extern "C" void kernel_launch(void* const* d_in, const int* in_sizes, int n_in,
                              void* d_out, int out_size) {
    (void)in_sizes; (void)n_in; (void)out_size;
    const float* x    = (const float*)d_in[0];
    // d_in[1] = adjacency (unused)
    const float* Wx   = (const float*)d_in[2];
    const float* Wh   = (const float*)d_in[3];
    const float* bias = (const float*)d_in[4];
    float* out = (float*)d_out;

    init_kernel<<<(Bn * Hn + 255) / 256, 256>>>();
    xg_gemm<<<Tn * 128, TPB>>>(x, Wx);
    recur_kernel<<<NBLK, TPB>>>(Wh, bias, out);
}

// round 6
// speedup vs baseline: 2.7333x; 2.7333x over previous
#include <cuda_runtime.h>
#include <math.h>
#include <stdint.h>

#define Bn 128
#define Tn 512
#define Dn 1024
#define Hn 1024
#define NBLK 128          // persistent recurrence CTAs (single wave)
#define KP   32           // K-panel depth

// ---------------- device scratch (no allocations allowed) ----------------
__device__ float g_xg[(size_t)Tn * 4 * Bn * Hn];   // [t][g][b][h], bias pre-added
__device__ float g_h[2][Bn * Hn];                  // ping-pong hidden state (fp32)
__device__ unsigned g_bar_count;
__device__ unsigned g_bar_gen;

__global__ void init_kernel() {
    int i = blockIdx.x * blockDim.x + threadIdx.x;
    if (i < Bn * Hn) g_h[0][i] = 0.0f;
}

// ---------------- grid barrier (round-4 proven) ----------------
__device__ __forceinline__ void grid_sync() {
    __threadfence();
    __syncthreads();
    if (threadIdx.x == 0) {
        unsigned gen = atomicAdd(&g_bar_gen, 0u);
        if (atomicAdd(&g_bar_count, 1u) == NBLK - 1) {
            g_bar_count = 0;
            __threadfence();
            atomicExch(&g_bar_gen, gen + 1);
        } else {
            int backoff = 32;
            while (atomicAdd(&g_bar_gen, 0u) == gen) {
                __nanosleep(backoff);
                if (backoff < 1024) backoff <<= 1;
            }
            __threadfence();
        }
    }
    __syncthreads();
}

// ---------------- tf32 helpers ----------------
__device__ __forceinline__ unsigned f2tf(float f) {
    unsigned r;
    asm("cvt.rna.tf32.f32 %0, %1;" : "=r"(r) : "f"(f));
    return r;
}

__device__ __forceinline__ void mma_tf32(float c[4], const unsigned a[4], const unsigned b[2]) {
    asm volatile(
        "mma.sync.aligned.m16n8k8.row.col.f32.tf32.tf32.f32 "
        "{%0,%1,%2,%3}, {%4,%5,%6,%7}, {%8,%9}, {%0,%1,%2,%3};"
        : "+f"(c[0]), "+f"(c[1]), "+f"(c[2]), "+f"(c[3])
        : "r"(a[0]), "r"(a[1]), "r"(a[2]), "r"(a[3]), "r"(b[0]), "r"(b[1]));
}

// =====================================================================
// Phase 1 (tensor cores): xg[t][g][b][h] = x[b][t][:] @ Wx[g][:,h] + bias
// grid = 32768: t*64 + (btile*32 + htile). CTA tile 64b x 128cols
// (4 gates x 32 h). 256 thr = 8 warps (2 warp-rows x 4 warp-cols),
// warp tile 32x32 = 2x4 m16n8k8 tiles. K-panel 32, register prefetch.
// =====================================================================
#define P1_TPB 256
__global__ __launch_bounds__(P1_TPB) void xg_gemm(const float* __restrict__ x,
                                                  const float* __restrict__ Wx,
                                                  const float* __restrict__ bias) {
    const int bid = blockIdx.x;
    const int t   = bid >> 6;
    const int rr  = bid & 63;
    const int b0  = (rr >> 5) * 64;
    const int h0  = (rr & 31) * 32;

    __shared__ unsigned As[64 * 36];    // [row][k], stride 36: conflict-free frag reads
    __shared__ unsigned Bs[32 * 136];   // [k][n],  stride 136: conflict-free frag reads

    const int tid  = threadIdx.x;
    const int lane = tid & 31;
    const int w    = tid >> 5;
    const int wr   = w >> 2;        // warp row (0..1) -> m offset wr*32
    const int wc   = w & 3;         // warp col (0..3) -> n offset wc*32 == gate wc

    // ---- loader coords ----
    const int ar  = tid >> 3;       // A rows ar and ar+32
    const int akg = tid & 7;        // A k-group (4 k each)
    const int c4  = tid & 31;       // B n-group (4 n each); kk = w + 8j
    const int bgN = c4 >> 3;
    const int bhh = (c4 & 7) * 4;

    const float* xr0 = x + ((size_t)(b0 + ar) * Tn + t) * Dn;
    const float* xr1 = x + ((size_t)(b0 + ar + 32) * Tn + t) * Dn;
    const float* wB  = Wx + (size_t)bgN * Dn * Hn + h0 + bhh;

    float c[2][4][4] = {};

    float4 pa0 = *(const float4*)&xr0[akg * 4];
    float4 pa1 = *(const float4*)&xr1[akg * 4];
    float4 pb[4];
#pragma unroll
    for (int j = 0; j < 4; j++)
        pb[j] = *(const float4*)&wB[(size_t)(w + 8 * j) * Hn];

    for (int k0 = 0; k0 < Dn; k0 += KP) {
        {   unsigned* d0 = &As[ar * 36 + akg * 4];
            d0[0] = f2tf(pa0.x); d0[1] = f2tf(pa0.y); d0[2] = f2tf(pa0.z); d0[3] = f2tf(pa0.w);
            unsigned* d1 = &As[(ar + 32) * 36 + akg * 4];
            d1[0] = f2tf(pa1.x); d1[1] = f2tf(pa1.y); d1[2] = f2tf(pa1.z); d1[3] = f2tf(pa1.w);
#pragma unroll
            for (int j = 0; j < 4; j++) {
                unsigned* d = &Bs[(w + 8 * j) * 136 + c4 * 4];
                d[0] = f2tf(pb[j].x); d[1] = f2tf(pb[j].y); d[2] = f2tf(pb[j].z); d[3] = f2tf(pb[j].w);
            }
        }
        __syncthreads();

        if (k0 + KP < Dn) {
            pa0 = *(const float4*)&xr0[k0 + KP + akg * 4];
            pa1 = *(const float4*)&xr1[k0 + KP + akg * 4];
#pragma unroll
            for (int j = 0; j < 4; j++)
                pb[j] = *(const float4*)&wB[(size_t)(k0 + KP + w + 8 * j) * Hn];
        }

#pragma unroll
        for (int ks = 0; ks < 4; ks++) {
            unsigned a[2][4];
#pragma unroll
            for (int mt = 0; mt < 2; mt++) {
                int R = wr * 32 + mt * 16 + (lane >> 2);
                int kc = ks * 8 + (lane & 3);
                a[mt][0] = As[R * 36 + kc];
                a[mt][1] = As[(R + 8) * 36 + kc];
                a[mt][2] = As[R * 36 + kc + 4];
                a[mt][3] = As[(R + 8) * 36 + kc + 4];
            }
            unsigned b[4][2];
#pragma unroll
            for (int nt = 0; nt < 4; nt++) {
                int col = wc * 32 + nt * 8 + (lane >> 2);
                int kb  = ks * 8 + (lane & 3);
                b[nt][0] = Bs[kb * 136 + col];
                b[nt][1] = Bs[(kb + 4) * 136 + col];
            }
#pragma unroll
            for (int mt = 0; mt < 2; mt++)
#pragma unroll
                for (int nt = 0; nt < 4; nt++)
                    mma_tf32(c[mt][nt], a[mt], b[nt]);
        }
        __syncthreads();
    }

    // epilogue: add bias, store float2 pairs (rows form 32B sectors)
    float bv0[4], bv1[4];
#pragma unroll
    for (int nt = 0; nt < 4; nt++) {
        int hc = h0 + nt * 8 + 2 * (lane & 3);
        bv0[nt] = bias[wc * Hn + hc];
        bv1[nt] = bias[wc * Hn + hc + 1];
    }
    float* outg = g_xg + ((size_t)t * 4 + wc) * (size_t)(Bn * Hn);
#pragma unroll
    for (int mt = 0; mt < 2; mt++) {
#pragma unroll
        for (int nt = 0; nt < 4; nt++) {
            int row = b0 + wr * 32 + mt * 16 + (lane >> 2);
            int hc  = h0 + nt * 8 + 2 * (lane & 3);
            float2 v0 = make_float2(c[mt][nt][0] + bv0[nt], c[mt][nt][1] + bv1[nt]);
            float2 v1 = make_float2(c[mt][nt][2] + bv0[nt], c[mt][nt][3] + bv1[nt]);
            *(float2*)&outg[(size_t)row * Hn + hc]       = v0;
            *(float2*)&outg[(size_t)(row + 8) * Hn + hc] = v1;
        }
    }
}

// =====================================================================
// Phase 2 (tensor cores): persistent recurrence. 128 CTAs x 128 thr
// (4 warps). CTA tile 32b x 128cols (warp wc = gate wc, 32 h cols).
// Warp tile 32x32 = 2x4 m16n8k8. c-state in registers. 1 barrier/step.
// =====================================================================
#define P2_TPB 128
__global__ __launch_bounds__(P2_TPB) void recur_kernel(const float* __restrict__ Wh,
                                                       float* __restrict__ out) {
    const int bid = blockIdx.x;
    const int b0  = (bid >> 5) * 32;
    const int h0  = (bid & 31) * 32;

    __shared__ unsigned As[32 * 36];
    __shared__ unsigned Bs[32 * 136];
    __shared__ float    gsm[4][32][36];

    const int tid  = threadIdx.x;
    const int lane = tid & 31;
    const int w    = tid >> 5;      // warp = gate = n-offset w*32
    const int wc   = w;

    // loader coords
    const int ar  = tid >> 3;       // A rows ar, ar+16
    const int akg = tid & 7;
    const int c4  = tid & 31;       // B: kk = w + 4j (j=0..7)
    const int bgN = c4 >> 3;
    const int bhh = (c4 & 7) * 4;

    const float* wB = Wh + (size_t)bgN * Hn * Hn + h0 + bhh;

    // cell-update ownership: row = tid>>2 (0..31), cols uh..uh+7
    const int urow = tid >> 2;
    const int uh   = (tid & 3) * 8;
    float cst[8] = {0.f, 0.f, 0.f, 0.f, 0.f, 0.f, 0.f, 0.f};

    for (int t = 0; t < Tn; t++) {
        const float* hprev = g_h[t & 1];
        float c[2][4][4] = {};

        float4 pa0 = *(const float4*)&hprev[(size_t)(b0 + ar) * Hn + akg * 4];
        float4 pa1 = *(const float4*)&hprev[(size_t)(b0 + ar + 16) * Hn + akg * 4];
        float4 pb[8];
#pragma unroll
        for (int j = 0; j < 8; j++)
            pb[j] = *(const float4*)&wB[(size_t)(w + 4 * j) * Hn];

        for (int k0 = 0; k0 < Hn; k0 += KP) {
            {   unsigned* d0 = &As[ar * 36 + akg * 4];
                d0[0] = f2tf(pa0.x); d0[1] = f2tf(pa0.y); d0[2] = f2tf(pa0.z); d0[3] = f2tf(pa0.w);
                unsigned* d1 = &As[(ar + 16) * 36 + akg * 4];
                d1[0] = f2tf(pa1.x); d1[1] = f2tf(pa1.y); d1[2] = f2tf(pa1.z); d1[3] = f2tf(pa1.w);
#pragma unroll
                for (int j = 0; j < 8; j++) {
                    unsigned* d = &Bs[(w + 4 * j) * 136 + c4 * 4];
                    d[0] = f2tf(pb[j].x); d[1] = f2tf(pb[j].y); d[2] = f2tf(pb[j].z); d[3] = f2tf(pb[j].w);
                }
            }
            __syncthreads();

            if (k0 + KP < Hn) {
                pa0 = *(const float4*)&hprev[(size_t)(b0 + ar) * Hn + k0 + KP + akg * 4];
                pa1 = *(const float4*)&hprev[(size_t)(b0 + ar + 16) * Hn + k0 + KP + akg * 4];
#pragma unroll
                for (int j = 0; j < 8; j++)
                    pb[j] = *(const float4*)&wB[(size_t)(k0 + KP + w + 4 * j) * Hn];
            }

#pragma unroll
            for (int ks = 0; ks < 4; ks++) {
                unsigned a[2][4];
#pragma unroll
                for (int mt = 0; mt < 2; mt++) {
                    int R = mt * 16 + (lane >> 2);
                    int kc = ks * 8 + (lane & 3);
                    a[mt][0] = As[R * 36 + kc];
                    a[mt][1] = As[(R + 8) * 36 + kc];
                    a[mt][2] = As[R * 36 + kc + 4];
                    a[mt][3] = As[(R + 8) * 36 + kc + 4];
                }
                unsigned b[4][2];
#pragma unroll
                for (int nt = 0; nt < 4; nt++) {
                    int col = wc * 32 + nt * 8 + (lane >> 2);
                    int kb  = ks * 8 + (lane & 3);
                    b[nt][0] = Bs[kb * 136 + col];
                    b[nt][1] = Bs[(kb + 4) * 136 + col];
                }
#pragma unroll
                for (int mt = 0; mt < 2; mt++)
#pragma unroll
                    for (int nt = 0; nt < 4; nt++)
                        mma_tf32(c[mt][nt], a[mt], b[nt]);
            }
            __syncthreads();
        }

        // stage Wh-GEMM result into gsm (gate = wc)
#pragma unroll
        for (int mt = 0; mt < 2; mt++)
#pragma unroll
            for (int nt = 0; nt < 4; nt++) {
                int row = mt * 16 + (lane >> 2);
                int col = nt * 8 + 2 * (lane & 3);
                *(float2*)&gsm[wc][row][col]     = make_float2(c[mt][nt][0], c[mt][nt][1]);
                *(float2*)&gsm[wc][row + 8][col] = make_float2(c[mt][nt][2], c[mt][nt][3]);
            }
        __syncthreads();

        // cell update on owned 1x8 strip (all 4 gates)
        float gate[4][8];
#pragma unroll
        for (int g = 0; g < 4; g++) {
            const float* xg = g_xg + (((size_t)t * 4 + g) * Bn + (b0 + urow)) * Hn + h0 + uh;
            float4 x0 = *(const float4*)&xg[0];
            float4 x1 = *(const float4*)&xg[4];
            float4 s0 = *(const float4*)&gsm[g][urow][uh];
            float4 s1 = *(const float4*)&gsm[g][urow][uh + 4];
            gate[g][0] = s0.x + x0.x; gate[g][1] = s0.y + x0.y;
            gate[g][2] = s0.z + x0.z; gate[g][3] = s0.w + x0.w;
            gate[g][4] = s1.x + x1.x; gate[g][5] = s1.y + x1.y;
            gate[g][6] = s1.z + x1.z; gate[g][7] = s1.w + x1.w;
        }
        float hv[8];
#pragma unroll
        for (int e = 0; e < 8; e++) {
            float i_ = 1.0f / (1.0f + expf(-gate[0][e]));
            float f_ = 1.0f / (1.0f + expf(-gate[1][e]));
            float o_ = 1.0f / (1.0f + expf(-gate[2][e]));
            float u_ = tanhf(gate[3][e]);
            cst[e] = f_ * cst[e] + i_ * u_;
            hv[e]  = o_ * tanhf(cst[e]);
        }
        float* hdst = (t == Tn - 1) ? out : g_h[(t + 1) & 1];
        float* hp = &hdst[(size_t)(b0 + urow) * Hn + h0 + uh];
        *(float4*)&hp[0] = make_float4(hv[0], hv[1], hv[2], hv[3]);
        *(float4*)&hp[4] = make_float4(hv[4], hv[5], hv[6], hv[7]);

        grid_sync();
    }
}

// ---------------- launch: 3 graph nodes ----------------
extern "C" void kernel_launch(void* const* d_in, const int* in_sizes, int n_in,
                              void* d_out, int out_size) {
    (void)in_sizes; (void)n_in; (void)out_size;
    const float* x    = (const float*)d_in[0];
    // d_in[1] = adjacency (unused)
    const float* Wx   = (const float*)d_in[2];
    const float* Wh   = (const float*)d_in[3];
    const float* bias = (const float*)d_in[4];
    float* out = (float*)d_out;

    init_kernel<<<(Bn * Hn + 255) / 256, 256>>>();
    xg_gemm<<<Tn * 64, P1_TPB>>>(x, Wx, bias);
    recur_kernel<<<NBLK, P2_TPB>>>(Wh, out);
}